// round 2
// baseline (speedup 1.0000x reference)
#include <cuda_runtime.h>
#include <cuda_bf16.h>
#include <cstdint>

// KernelDensityEstimate. With var=0.5 and N(0,1) data, ||a-b||^2 ~ 256 +- 32;
// fp32 exp underflows below -103.97 so essentially every density is 0 in the
// reference. Screen with bf16 tensor-core GEMM (worst-case exponent error
// <= ~2.7) and recompute exactly (fp32 dot + expf) only when the screened
// exponent > -115. That branch is ~never taken.

#define N_ROWS 4096
#define M_CL   128
#define Q_PTS  64
#define D_DIM  128
#define MQ     (M_CL * Q_PTS)

#define SA 136   // padded bf16 row stride (272B: 16B-aligned, conflict-free)

// Scratch (allocation-free rule: __device__ globals)
__device__ __nv_bfloat16 g_Abf[N_ROWS * D_DIM];
__device__ __nv_bfloat16 g_Bbf[MQ * D_DIM];
__device__ float g_a2[N_ROWS];
__device__ float g_b2[MQ];
__device__ float g_dens[N_ROWS * M_CL];

__device__ __forceinline__ float warp_sum(float v) {
#pragma unroll
    for (int o = 16; o > 0; o >>= 1) v += __shfl_xor_sync(0xffffffffu, v, o);
    return v;
}

// ---------------------------------------------------------------------------
// Prep: one kernel, warp-per-row. Lane holds float4 (128 floats = 32 float4).
// Converts to bf16 (packed 8B store) and computes the row squared norm.
// Rows 0..4095 -> A, 4096..12287 -> B.
// ---------------------------------------------------------------------------
__global__ void __launch_bounds__(256) prep_kernel(
    const float* __restrict__ A, const float* __restrict__ B)
{
    const int warp = threadIdx.x >> 5, lane = threadIdx.x & 31;
    const int row = blockIdx.x * 8 + warp;          // 0..12287

    const float* src;
    __nv_bfloat16* dst;
    float* nrm;
    if (row < N_ROWS) {
        src = A + (size_t)row * D_DIM;
        dst = g_Abf + (size_t)row * D_DIM;
        nrm = g_a2 + row;
    } else {
        int r = row - N_ROWS;
        src = B + (size_t)r * D_DIM;
        dst = g_Bbf + (size_t)r * D_DIM;
        nrm = g_b2 + r;
    }

    float4 v = ((const float4*)src)[lane];
    float s = warp_sum(v.x * v.x + v.y * v.y + v.z * v.z + v.w * v.w);

    __nv_bfloat162 p0 = __floats2bfloat162_rn(v.x, v.y);
    __nv_bfloat162 p1 = __floats2bfloat162_rn(v.z, v.w);
    uint2 packed;
    packed.x = *(const uint32_t*)&p0;
    packed.y = *(const uint32_t*)&p1;
    ((uint2*)dst)[lane] = packed;

    if (lane == 0) *nrm = s;
}

// ---------------------------------------------------------------------------
// Main: block computes dens[n0..n0+127, m0..m0+1] (q-tile = 128 = 2 clusters).
// 8 warps: (wn 0..3) x (wq 0..1); warp tile 32n x 64q (one full cluster in q),
// so the per-(row,m) q-sum lives entirely inside one warp.
// mma.sync.m16n8k16 bf16: 2 m-tiles x 8 n-tiles x 8 k-steps = 128 MMA/warp.
// ---------------------------------------------------------------------------
__global__ void __launch_bounds__(256, 2) kde_main_kernel(
    const float* __restrict__ A, const float* __restrict__ B,
    const float* __restrict__ var_ptr)
{
    extern __shared__ char smem_raw[];
    __nv_bfloat16* As = (__nv_bfloat16*)smem_raw;                      // 128 x SA
    __nv_bfloat16* Bs = (__nv_bfloat16*)(smem_raw + 128 * SA * 2);     // 128 x SA
    float* a2s   = (float*)(smem_raw + 2 * 128 * SA * 2);              // 128
    float* b2s   = a2s + 128;                                          // 128
    float* sdens = b2s + 128;                                          // 128 x 2

    const int tid  = threadIdx.x;
    const int lane = tid & 31, warp = tid >> 5;
    const int wn = warp >> 1, wq = warp & 1;
    const int g = lane >> 2, tig = lane & 3;
    const int n0 = blockIdx.x * 128;
    const int q0 = blockIdx.y * 128;                 // global q base (m0 = q0/64)

    // Load tiles (coalesced uint4: 2048 each, 8 iters at 256 threads)
    {
        const uint4* srcA = (const uint4*)(g_Abf + (size_t)n0 * D_DIM);
        const uint4* srcB = (const uint4*)(g_Bbf + (size_t)q0 * D_DIM);
#pragma unroll
        for (int i = 0; i < 8; i++) {
            int idx = tid + i * 256;                 // 0..2047
            int r = idx >> 4, c = idx & 15;
            *((uint4*)(As + r * SA) + c) = srcA[r * 16 + c];
        }
#pragma unroll
        for (int i = 0; i < 8; i++) {
            int idx = tid + i * 256;
            int r = idx >> 4, c = idx & 15;
            *((uint4*)(Bs + r * SA) + c) = srcB[r * 16 + c];
        }
        if (tid < 128) {
            a2s[tid] = g_a2[n0 + tid];
            b2s[tid] = g_b2[q0 + tid];
        }
    }
    __syncthreads();

    float c[2][8][4];
#pragma unroll
    for (int mt = 0; mt < 2; mt++)
#pragma unroll
        for (int nt = 0; nt < 8; nt++)
#pragma unroll
            for (int i = 0; i < 4; i++) c[mt][nt][i] = 0.0f;

#pragma unroll
    for (int ks = 0; ks < 8; ks++) {
        const int kb = ks * 16 + tig * 2;
        uint32_t a[2][4];
#pragma unroll
        for (int mt = 0; mt < 2; mt++) {
            int r = wn * 32 + mt * 16 + g;
            const __nv_bfloat16* pr0 = As + r * SA;
            const __nv_bfloat16* pr1 = As + (r + 8) * SA;
            a[mt][0] = *(const uint32_t*)(pr0 + kb);
            a[mt][1] = *(const uint32_t*)(pr1 + kb);
            a[mt][2] = *(const uint32_t*)(pr0 + kb + 8);
            a[mt][3] = *(const uint32_t*)(pr1 + kb + 8);
        }
#pragma unroll
        for (int nt = 0; nt < 8; nt++) {
            int col = wq * 64 + nt * 8 + g;
            const __nv_bfloat16* pc = Bs + col * SA;
            uint32_t b0 = *(const uint32_t*)(pc + kb);
            uint32_t b1 = *(const uint32_t*)(pc + kb + 8);
#pragma unroll
            for (int mt = 0; mt < 2; mt++) {
                asm volatile(
                    "mma.sync.aligned.m16n8k16.row.col.f32.bf16.bf16.f32 "
                    "{%0,%1,%2,%3}, {%4,%5,%6,%7}, {%8,%9}, {%0,%1,%2,%3};\n"
                    : "+f"(c[mt][nt][0]), "+f"(c[mt][nt][1]),
                      "+f"(c[mt][nt][2]), "+f"(c[mt][nt][3])
                    : "r"(a[mt][0]), "r"(a[mt][1]), "r"(a[mt][2]), "r"(a[mt][3]),
                      "r"(b0), "r"(b1));
            }
        }
    }

    // Epilogue: exponent screen + (rare) exact fp32 recompute, sum over q.
    const float inv_var = 1.0f / var_ptr[0];
    const float sc = -0.5f * inv_var;

    float acc[2][2] = {{0.0f, 0.0f}, {0.0f, 0.0f}};   // [mt][rs]
#pragma unroll
    for (int mt = 0; mt < 2; mt++) {
#pragma unroll
        for (int rs = 0; rs < 2; rs++) {
            const float a2v = a2s[wn * 32 + mt * 16 + rs * 8 + g];
#pragma unroll
            for (int nt = 0; nt < 8; nt++) {
#pragma unroll
                for (int u = 0; u < 2; u++) {
                    // c regs: [0]=(g,2t) [1]=(g,2t+1) [2]=(g+8,2t) [3]=(g+8,2t+1)
                    float ab  = c[mt][nt][rs * 2 + u];
                    int qloc  = wq * 64 + nt * 8 + tig * 2 + u;
                    float e   = sc * (a2v - 2.0f * ab + b2s[qloc]);
                    float contrib = 0.0f;
                    if (e > -115.0f) {   // screen margin >> worst-case bf16 error
                        int n_glob = n0 + wn * 32 + mt * 16 + rs * 8 + g;
                        int qg = q0 + qloc;
                        const float* ar = A + (size_t)n_glob * D_DIM;
                        const float* br = B + (size_t)qg * D_DIM;
                        float dot = 0.0f;
                        for (int k = 0; k < D_DIM; k++) dot = fmaf(ar[k], br[k], dot);
                        float ee = sc * (a2v - 2.0f * dot + b2s[qloc]);
                        contrib = expf(ee);
                    }
                    acc[mt][rs] += contrib;
                }
            }
        }
    }

    // Reduce q-partials across tig (lanes tig 0..3 share a row); each warp
    // covers one full cluster (m_local = wq), so no cross-warp combine.
#pragma unroll
    for (int mt = 0; mt < 2; mt++) {
#pragma unroll
        for (int rs = 0; rs < 2; rs++) {
            float v = acc[mt][rs];
            v += __shfl_xor_sync(0xffffffffu, v, 1);
            v += __shfl_xor_sync(0xffffffffu, v, 2);
            if (tig == 0)
                sdens[(wn * 32 + mt * 16 + rs * 8 + g) * 2 + wq] = v;
        }
    }
    __syncthreads();
    {
        int row = tid >> 1, ml = tid & 1;            // 256 threads -> 128x2
        int m = blockIdx.y * 2 + ml;
        g_dens[(size_t)(n0 + row) * M_CL + m] = sdens[row * 2 + ml];
    }
}

// ---------------------------------------------------------------------------
// Normalize: warp-per-row, float4. prob = dens / (sum_m dens + 1e-10).
// ---------------------------------------------------------------------------
__global__ void __launch_bounds__(256) norm_kernel(float* __restrict__ out) {
    const int warp = threadIdx.x >> 5, lane = threadIdx.x & 31;
    const int n = blockIdx.x * 8 + warp;
    float4 d = ((const float4*)(g_dens + (size_t)n * M_CL))[lane];
    float tot = warp_sum(d.x + d.y + d.z + d.w) + 1e-10f;
    float inv = 1.0f / tot;
    float4 o = make_float4(d.x * inv, d.y * inv, d.z * inv, d.w * inv);
    ((float4*)(out + (size_t)n * M_CL))[lane] = o;
}

// ---------------------------------------------------------------------------
extern "C" void kernel_launch(void* const* d_in, const int* in_sizes, int n_in,
                              void* d_out, int out_size) {
    const float* A   = (const float*)d_in[0];   // [4096,128]
    const float* B   = (const float*)d_in[1];   // [128,64,128]
    const float* var = (const float*)d_in[2];   // [1]
    float* out = (float*)d_out;                 // [4096,128]

    const size_t smem = 2 * 128 * SA * 2 + (128 + 128 + 256) * sizeof(float);
    cudaFuncSetAttribute(kde_main_kernel,
                         cudaFuncAttributeMaxDynamicSharedMemorySize, (int)smem);

    prep_kernel<<<(N_ROWS + MQ) / 8, 256>>>(A, B);

    dim3 grid(N_ROWS / 128, MQ / 128);
    kde_main_kernel<<<grid, 256, smem>>>(A, B, var);

    norm_kernel<<<N_ROWS / 8, 256>>>(out);
}